// round 16
// baseline (speedup 1.0000x reference)
#include <cuda_runtime.h>
#include <cuda_fp16.h>
#include <cstdint>

// Problem constants: B=4, N=4096, PD=1024, D=16, S=64
#define NN   4096
#define PD   1024
#define ALLC 1024
#define MROWS 16384

// Scratch (device globals; allocation-free rule)
__device__ __half g_P[(size_t)MROWS * 2 * ALLC];    //  64 MB (GEMM1 out, fp16)
__device__ __half g_Q[(size_t)MROWS * ALLC];        //  32 MB (middle out, fp16)
__device__ __half g_xh[(size_t)MROWS * PD];         //  33 MB x in fp16
__device__ __half g_Wrt[(size_t)2 * ALLC * PD];     //   4 MB W_r^T fp16 (K contig)
__device__ __half g_Wwt[(size_t)PD * ALLC];         //   2 MB W_w^T fp16

// ---------------------------------------------------------------------------
// Helpers
// ---------------------------------------------------------------------------
__device__ __forceinline__ uint32_t smem_u32(const void* p) {
    uint32_t a;
    asm("{ .reg .u64 t; cvta.to.shared.u64 t, %1; cvt.u32.u64 %0, t; }"
        : "=r"(a) : "l"(p));
    return a;
}
__device__ __forceinline__ void cp_async16(uint32_t s, const void* g) {
    asm volatile("cp.async.cg.shared.global [%0], [%1], 16;" :: "r"(s), "l"(g));
}
#define CP_COMMIT() asm volatile("cp.async.commit_group;" ::: "memory")
#define CP_WAIT(n)  asm volatile("cp.async.wait_group %0;" :: "n"(n) : "memory")

#define LDSM4(R0, R1, R2, R3, A) \
    asm volatile("ldmatrix.sync.aligned.m8n8.x4.shared.b16 {%0,%1,%2,%3}, [%4];" \
        : "=r"(R0), "=r"(R1), "=r"(R2), "=r"(R3) : "r"(A))

__device__ __forceinline__ void mma16(float* c, const uint32_t* a, const uint32_t* b) {
    asm volatile(
        "mma.sync.aligned.m16n8k16.row.col.f32.f16.f16.f32 "
        "{%0,%1,%2,%3}, {%4,%5,%6,%7}, {%8,%9}, {%0,%1,%2,%3};"
        : "+f"(c[0]), "+f"(c[1]), "+f"(c[2]), "+f"(c[3])
        : "r"(a[0]), "r"(a[1]), "r"(a[2]), "r"(a[3]), "r"(b[0]), "r"(b[1]));
}

// ---------------------------------------------------------------------------
// fp16 mma.sync GEMM, C fp16 or fp32 (template).
// CTA 128(M) x 256(N), BK=64, 256 threads = 8 warps of 64x64 (2m x 4n grid).
// Warp tile 64x64 cuts ldmatrix redundancy 1.5x vs 64x32 (A x2, B x2).
// 3-stage cp.async, stores interleaved into the 4 k16-steps (3/thread/step).
// ROW_B=144: (9r+c) mod 8 bijective -> stores + all ldmatrix phases
// conflict-free (proven since R12; only extended to 4 B-groups).
// ---------------------------------------------------------------------------
#define STAGES 3
#define ROW_B 144
#define A_STAGE (128 * ROW_B)                  // 18432 B
#define B_STAGE (256 * ROW_B)                  // 36864 B
#define STAGE_BYTES (A_STAGE + B_STAGE)        // 55296 B
#define GEMM_SMEM (STAGES * STAGE_BYTES)       // 165888 B

template <typename CT>
__global__ __launch_bounds__(256, 1)
void gemm_f16(const __half* __restrict__ A, const __half* __restrict__ Bt,
              const float* __restrict__ bias, CT* __restrict__ C,
              int Ncol, int K)
{
    extern __shared__ char sm[];
    const uint32_t sb = smem_u32(sm);
    const int tid = threadIdx.x;
    const int w   = tid >> 5, l = tid & 31;
    const int wm  = w >> 2,  wn = w & 3;       // 2(m) x 4(n)
    const int m0  = blockIdx.y * 128;
    const int n0  = blockIdx.x * 256;

    const __half* Ag = A  + (size_t)m0 * K;
    const __half* Bg = Bt + (size_t)n0 * K;

    float acc[4][8][4];                         // 4 m16-tiles x 8 n8-tiles
    #pragma unroll
    for (int i = 0; i < 4; i++)
        #pragma unroll
        for (int j = 0; j < 8; j++)
            #pragma unroll
            for (int k = 0; k < 4; k++) acc[i][j][k] = 0.f;

    // Per chunk: A 128 rows (4 ops/thr), B 256 rows (8 ops/thr) -> 12/thread.
    // Slice p (0..3): 1 A row-block + 2 B row-blocks (3 cp.async).
    const int ldr = tid >> 3, ldc = tid & 7;    // row base 0..31, 16B col 0..7
    auto load_slice = [&](int kc, int st, int p) {
        const uint32_t sA = sb + (uint32_t)st * STAGE_BYTES;
        const uint32_t sB = sA + A_STAGE;
        const int arow = p * 32 + ldr;
        cp_async16(sA + arow * ROW_B + ldc * 16,
                   Ag + (size_t)arow * K + kc * 64 + ldc * 8);
        const int brow = p * 64 + ldr;
        cp_async16(sB + brow * ROW_B + ldc * 16,
                   Bg + (size_t)brow * K + kc * 64 + ldc * 8);
        cp_async16(sB + (brow + 32) * ROW_B + ldc * 16,
                   Bg + (size_t)(brow + 32) * K + kc * 64 + ldc * 8);
    };
    auto load_chunk = [&](int kc, int st) {
        #pragma unroll
        for (int p = 0; p < 4; p++) load_slice(kc, st, p);
    };

    const int KCH = K >> 6;
    #pragma unroll
    for (int j = 0; j < STAGES - 1; j++) { load_chunk(j, j); CP_COMMIT(); }

    // ldmatrix per-thread offsets (identical algebra since R12)
    const uint32_t aoff = (uint32_t)(wm * 64 + (l & 15)) * ROW_B + (l >> 4) * 16;
    const uint32_t boff = (uint32_t)(wn * 64 + ((l >> 4) << 3) + (l & 7)) * ROW_B
                        + ((l >> 3) & 1) * 16;

    for (int kc = 0; kc < KCH; kc++) {
        CP_WAIT(STAGES - 2);                    // chunk kc resident
        __syncthreads();                        // stage (kc+2)%3 free to overwrite

        const int jl = kc + STAGES - 1;
        const int sl = jl % STAGES;
        const bool doload = (jl < KCH);
        const uint32_t base  = sb + (uint32_t)(kc % STAGES) * STAGE_BYTES;
        const uint32_t baseB = base + A_STAGE;

        #pragma unroll
        for (int s2 = 0; s2 < 4; s2++) {        // four k16 steps
            uint32_t a[4][4], b[8][2];
            #pragma unroll
            for (int i = 0; i < 4; i++)
                LDSM4(a[i][0], a[i][1], a[i][2], a[i][3],
                      base + aoff + (uint32_t)i * 16 * ROW_B + s2 * 32);
            #pragma unroll
            for (int jp = 0; jp < 4; jp++) {
                uint32_t r0, r1, r2, r3;
                LDSM4(r0, r1, r2, r3,
                      baseB + boff + (uint32_t)jp * 16 * ROW_B + s2 * 32);
                b[2 * jp][0] = r0; b[2 * jp][1] = r1;
                b[2 * jp + 1][0] = r2; b[2 * jp + 1][1] = r3;
            }
            if (doload) load_slice(jl, sl, s2); // smooth stores into slack
            #pragma unroll
            for (int i = 0; i < 4; i++)
                #pragma unroll
                for (int j = 0; j < 8; j++)
                    mma16(acc[i][j], a[i], b[j]);
        }
        CP_COMMIT();                            // one group per iteration
    }

    // Epilogue: bias + vectorized stores
    const int grp = l >> 2, quad = l & 3;
    #pragma unroll
    for (int i = 0; i < 4; i++) {
        const int r = m0 + wm * 64 + i * 16 + grp;
        #pragma unroll
        for (int j = 0; j < 8; j++) {
            const int c = n0 + wn * 64 + j * 8 + quad * 2;
            float2 bv = *(const float2*)(bias + c);
            float p0 = acc[i][j][0] + bv.x, p1 = acc[i][j][1] + bv.y;
            float p2 = acc[i][j][2] + bv.x, p3 = acc[i][j][3] + bv.y;
            if (sizeof(CT) == 2) {
                __half2 h0 = __floats2half2_rn(p0, p1);
                __half2 h1 = __floats2half2_rn(p2, p3);
                *(__half2*)((__half*)C + (size_t)r * Ncol + c)       = h0;
                *(__half2*)((__half*)C + (size_t)(r + 8) * Ncol + c) = h1;
            } else {
                float2 v0 = { p0, p1 }, v1 = { p2, p3 };
                *(float2*)((float*)C + (size_t)r * Ncol + c)       = v0;
                *(float2*)((float*)C + (size_t)(r + 8) * Ncol + c) = v1;
            }
        }
    }
}

// ---------------------------------------------------------------------------
// f32 -> f16 convert (for x)
// ---------------------------------------------------------------------------
__global__ __launch_bounds__(256)
void convert_h(const float* __restrict__ in, __half* __restrict__ out, int n4)
{
    int i = blockIdx.x * 256 + threadIdx.x;
    if (i < n4) {
        float4 v = ((const float4*)in)[i];
        __half2 h0 = __floats2half2_rn(v.x, v.y);
        __half2 h1 = __floats2half2_rn(v.z, v.w);
        uint2 o = { *(uint32_t*)&h0, *(uint32_t*)&h1 };
        ((uint2*)out)[i] = o;
    }
}

// ---------------------------------------------------------------------------
// Transpose + f16 rounding: out[C][R] = f16(in[R][C])
// ---------------------------------------------------------------------------
__global__ __launch_bounds__(256)
void transpose_k(const float* __restrict__ in, __half* __restrict__ out,
                 int R, int C)
{
    __shared__ float t[32][33];
    const int bx = blockIdx.x * 32, by = blockIdx.y * 32;
    #pragma unroll
    for (int i = 0; i < 4; i++)
        t[threadIdx.y + i * 8][threadIdx.x] =
            in[(size_t)(by + threadIdx.y + i * 8) * C + bx + threadIdx.x];
    __syncthreads();
    #pragma unroll
    for (int i = 0; i < 4; i++)
        out[(size_t)(bx + threadIdx.y + i * 8) * R + by + threadIdx.x] =
            __float2half_rn(t[threadIdx.x][threadIdx.y + i * 8]);
}

// ---------------------------------------------------------------------------
// Middle op (math proven since R3; P fp16 since R14):
//   p = softmax_16(P0 row); Q[b,n,d*64+s] = sum_a p[a]*P1[b,n+a+1,d-1-a,s]
// ---------------------------------------------------------------------------
__global__ __launch_bounds__(256)
void middle_kernel(const __half* __restrict__ P, __half* __restrict__ Q)
{
    const int s   = threadIdx.x & 63;
    const int sub = threadIdx.x >> 6;
    const int bn  = blockIdx.x * 4 + sub;
    const int n   = bn & (NN - 1);
    const int t   = n & 15;
    const int g   = n >> 4;
    const bool last = (g == (NN / 16) - 1);

    const __half* base = P + (size_t)bn * (2 * ALLC) + s;

    float v[16];
    float m = -1e30f;
    #pragma unroll
    for (int k = 0; k < 16; k++) { v[k] = __half2float(base[k * 64]); m = fmaxf(m, v[k]); }
    float sum = 0.f;
    #pragma unroll
    for (int k = 0; k < 16; k++) { v[k] = __expf(v[k] - m); sum += v[k]; }
    const float inv = 1.0f / sum;

    float out[16];
    #pragma unroll
    for (int d = 0; d < 16; d++) out[d] = 0.f;

    const __half* r0 = base + ALLC + 2 * ALLC;

    if (!last) {
        #pragma unroll
        for (int a = 0; a < 15; a++) {
            const float pa = v[a] * inv;
            const __half* ra = r0 + (size_t)a * (2 * ALLC);
            #pragma unroll
            for (int c = 0; c < 15 - a; c++)
                out[a + 1 + c] += pa * __half2float(ra[c * 64]);
        }
    } else {
        const int dmax = 15 - t;
        #pragma unroll
        for (int a = 0; a < 15; a++) {
            const float pa = v[a] * inv;
            const __half* ra = r0 + (size_t)a * (2 * ALLC);
            #pragma unroll
            for (int c = 0; c < 15 - a; c++)
                if (a + 1 + c <= dmax)
                    out[a + 1 + c] += pa * __half2float(ra[c * 64]);
        }
    }

    __half* q = Q + (size_t)bn * ALLC + s;
    #pragma unroll
    for (int d = 0; d < 16; d++) q[d * 64] = __float2half_rn(out[d]);
}

// ---------------------------------------------------------------------------
extern "C" void kernel_launch(void* const* d_in, const int* in_sizes, int n_in,
                              void* d_out, int out_size)
{
    const float* x   = (const float*)d_in[0];
    const float* W_r = (const float*)d_in[1];
    const float* b_r = (const float*)d_in[2];
    const float* W_w = (const float*)d_in[3];
    const float* b_w = (const float*)d_in[4];
    float* out = (float*)d_out;

    __half *P, *Q, *xh, *Wrt, *Wwt;
    cudaGetSymbolAddress((void**)&P,   g_P);
    cudaGetSymbolAddress((void**)&Q,   g_Q);
    cudaGetSymbolAddress((void**)&xh,  g_xh);
    cudaGetSymbolAddress((void**)&Wrt, g_Wrt);
    cudaGetSymbolAddress((void**)&Wwt, g_Wwt);

    cudaFuncSetAttribute(gemm_f16<__half>,
                         cudaFuncAttributeMaxDynamicSharedMemorySize, GEMM_SMEM);
    cudaFuncSetAttribute(gemm_f16<float>,
                         cudaFuncAttributeMaxDynamicSharedMemorySize, GEMM_SMEM);

    // x -> fp16; weight transposes (+ fp16 rounding)
    const int n4 = MROWS * PD / 4;
    convert_h<<<(n4 + 255) / 256, 256>>>(x, xh, n4);
    transpose_k<<<dim3(2 * ALLC / 32, PD / 32), dim3(32, 8)>>>(W_r, Wrt, PD, 2 * ALLC);
    transpose_k<<<dim3(PD / 32, ALLC / 32),     dim3(32, 8)>>>(W_w, Wwt, ALLC, PD);

    // GEMM1: P(fp16) = x @ W_r + b_r   (16384 x 2048 x 1024)
    gemm_f16<__half><<<dim3(2 * ALLC / 256, MROWS / 128), 256, GEMM_SMEM>>>(
        xh, Wrt, b_r, P, 2 * ALLC, PD);

    // Middle: softmax + stencil -> Q (fp16)
    middle_kernel<<<MROWS / 4, 256>>>(P, Q);

    // GEMM2: out(f32) = Q @ W_w + b_w  (16384 x 1024 x 1024)
    gemm_f16<float><<<dim3(PD / 256, MROWS / 128), 256, GEMM_SMEM>>>(
        Q, Wwt, b_w, out, PD, ALLC);
}

// round 17
// speedup vs baseline: 1.0986x; 1.0986x over previous
#include <cuda_runtime.h>
#include <cuda_fp16.h>
#include <cstdint>

// Problem constants: B=4, N=4096, PD=1024, D=16, S=64
#define NN   4096
#define PD   1024
#define ALLC 1024
#define MROWS 16384

// Scratch (device globals; allocation-free rule)
__device__ __half g_P[(size_t)MROWS * 2 * ALLC];    //  64 MB (GEMM1 out, fp16)
__device__ __half g_Q[(size_t)MROWS * ALLC];        //  32 MB (middle out, fp16)
__device__ __half g_xh[(size_t)MROWS * PD];         //  33 MB x in fp16
__device__ __half g_Wrt[(size_t)2 * ALLC * PD];     //   4 MB W_r^T fp16 (K contig)
__device__ __half g_Wwt[(size_t)PD * ALLC];         //   2 MB W_w^T fp16

// ---------------------------------------------------------------------------
// Helpers
// ---------------------------------------------------------------------------
__device__ __forceinline__ uint32_t smem_u32(const void* p) {
    uint32_t a;
    asm("{ .reg .u64 t; cvta.to.shared.u64 t, %1; cvt.u32.u64 %0, t; }"
        : "=r"(a) : "l"(p));
    return a;
}
__device__ __forceinline__ void cp_async16(uint32_t s, const void* g) {
    asm volatile("cp.async.cg.shared.global [%0], [%1], 16;" :: "r"(s), "l"(g));
}
#define CP_COMMIT() asm volatile("cp.async.commit_group;" ::: "memory")
#define CP_WAIT(n)  asm volatile("cp.async.wait_group %0;" :: "n"(n) : "memory")

#define LDSM4(R0, R1, R2, R3, A) \
    asm volatile("ldmatrix.sync.aligned.m8n8.x4.shared.b16 {%0,%1,%2,%3}, [%4];" \
        : "=r"(R0), "=r"(R1), "=r"(R2), "=r"(R3) : "r"(A))

__device__ __forceinline__ void mma16(float* c, const uint32_t* a, const uint32_t* b) {
    asm volatile(
        "mma.sync.aligned.m16n8k16.row.col.f32.f16.f16.f32 "
        "{%0,%1,%2,%3}, {%4,%5,%6,%7}, {%8,%9}, {%0,%1,%2,%3};"
        : "+f"(c[0]), "+f"(c[1]), "+f"(c[2]), "+f"(c[3])
        : "r"(a[0]), "r"(a[1]), "r"(a[2]), "r"(a[3]), "r"(b[0]), "r"(b[1]));
}

// ---------------------------------------------------------------------------
// fp16 mma.sync GEMM, C fp16 or fp32 (template).
// CTA 128x128, BK=64, 128 threads = 4 warps of 64x64 (2m x 2n grid),
// 2 CTAs/SM (the R15 regression was 1-CTA residency, not the 64x64 tile).
// 3-stage cp.async, 4 cp.async/thread interleaved into each k16-step.
// ROW_B=144: (9r+c) mod 8 bijective -> stores + all ldmatrix phases
// conflict-free (proven since R12).
// ---------------------------------------------------------------------------
#define STAGES 3
#define ROW_B 144
#define A_STAGE (128 * ROW_B)                  // 18432 B
#define STAGE_BYTES (2 * A_STAGE)              // 36864 B (A + B halves)
#define GEMM_SMEM (STAGES * STAGE_BYTES)       // 110592 B -> 2 CTAs = 216 KB

template <typename CT>
__global__ __launch_bounds__(128, 2)
void gemm_f16(const __half* __restrict__ A, const __half* __restrict__ Bt,
              const float* __restrict__ bias, CT* __restrict__ C,
              int Ncol, int K)
{
    extern __shared__ char sm[];
    const uint32_t sb = smem_u32(sm);
    const int tid = threadIdx.x;
    const int w   = tid >> 5, l = tid & 31;
    const int wm  = w >> 1,  wn = w & 1;       // 2(m) x 2(n), 64x64 each
    const int m0  = blockIdx.y * 128;
    const int n0  = blockIdx.x * 128;

    const __half* Ag = A  + (size_t)m0 * K;
    const __half* Bg = Bt + (size_t)n0 * K;

    float acc[4][8][4];                         // 4 m16-tiles x 8 n8-tiles
    #pragma unroll
    for (int i = 0; i < 4; i++)
        #pragma unroll
        for (int j = 0; j < 8; j++)
            #pragma unroll
            for (int k = 0; k < 4; k++) acc[i][j][k] = 0.f;

    // Per chunk: A 128 rows x 8 16B-cols = 1024 ops; same for B -> 16/thread.
    // Slice p (0..3): 2 A rows + 2 B rows (4 cp.async), interleaved per k-step.
    const int ldr = tid >> 3, ldc = tid & 7;    // row base 0..15, 16B col 0..7
    auto load_slice = [&](int kc, int st, int p) {
        const uint32_t sA = sb + (uint32_t)st * STAGE_BYTES;
        const uint32_t sB = sA + A_STAGE;
        const int r0 = p * 32 + ldr, r1 = r0 + 16;
        cp_async16(sA + r0 * ROW_B + ldc * 16,
                   Ag + (size_t)r0 * K + kc * 64 + ldc * 8);
        cp_async16(sA + r1 * ROW_B + ldc * 16,
                   Ag + (size_t)r1 * K + kc * 64 + ldc * 8);
        cp_async16(sB + r0 * ROW_B + ldc * 16,
                   Bg + (size_t)r0 * K + kc * 64 + ldc * 8);
        cp_async16(sB + r1 * ROW_B + ldc * 16,
                   Bg + (size_t)r1 * K + kc * 64 + ldc * 8);
    };
    auto load_chunk = [&](int kc, int st) {
        #pragma unroll
        for (int p = 0; p < 4; p++) load_slice(kc, st, p);
    };

    const int KCH = K >> 6;
    #pragma unroll
    for (int j = 0; j < STAGES - 1; j++) { load_chunk(j, j); CP_COMMIT(); }

    // ldmatrix per-thread offsets (algebra proven since R12)
    const uint32_t aoff = (uint32_t)(wm * 64 + (l & 15)) * ROW_B + (l >> 4) * 16;
    const uint32_t boff = (uint32_t)(wn * 64 + ((l >> 4) << 3) + (l & 7)) * ROW_B
                        + ((l >> 3) & 1) * 16;

    for (int kc = 0; kc < KCH; kc++) {
        CP_WAIT(STAGES - 2);                    // chunk kc resident
        __syncthreads();                        // stage (kc+2)%3 free to overwrite

        const int jl = kc + STAGES - 1;
        const int sl = jl % STAGES;
        const bool doload = (jl < KCH);
        const uint32_t base  = sb + (uint32_t)(kc % STAGES) * STAGE_BYTES;
        const uint32_t baseB = base + A_STAGE;

        #pragma unroll
        for (int s2 = 0; s2 < 4; s2++) {        // four k16 steps
            uint32_t a[4][4], b[8][2];
            #pragma unroll
            for (int i = 0; i < 4; i++)
                LDSM4(a[i][0], a[i][1], a[i][2], a[i][3],
                      base + aoff + (uint32_t)i * 16 * ROW_B + s2 * 32);
            #pragma unroll
            for (int jp = 0; jp < 4; jp++) {
                uint32_t r0, r1, r2, r3;
                LDSM4(r0, r1, r2, r3,
                      baseB + boff + (uint32_t)jp * 16 * ROW_B + s2 * 32);
                b[2 * jp][0] = r0; b[2 * jp][1] = r1;
                b[2 * jp + 1][0] = r2; b[2 * jp + 1][1] = r3;
            }
            if (doload) load_slice(jl, sl, s2); // smooth stores into slack
            #pragma unroll
            for (int i = 0; i < 4; i++)
                #pragma unroll
                for (int j = 0; j < 8; j++)
                    mma16(acc[i][j], a[i], b[j]);
        }
        CP_COMMIT();                            // one group per iteration
    }

    // Epilogue: bias + vectorized stores
    const int grp = l >> 2, quad = l & 3;
    #pragma unroll
    for (int i = 0; i < 4; i++) {
        const int r = m0 + wm * 64 + i * 16 + grp;
        #pragma unroll
        for (int j = 0; j < 8; j++) {
            const int c = n0 + wn * 64 + j * 8 + quad * 2;
            float2 bv = *(const float2*)(bias + c);
            float p0 = acc[i][j][0] + bv.x, p1 = acc[i][j][1] + bv.y;
            float p2 = acc[i][j][2] + bv.x, p3 = acc[i][j][3] + bv.y;
            if (sizeof(CT) == 2) {
                __half2 h0 = __floats2half2_rn(p0, p1);
                __half2 h1 = __floats2half2_rn(p2, p3);
                *(__half2*)((__half*)C + (size_t)r * Ncol + c)       = h0;
                *(__half2*)((__half*)C + (size_t)(r + 8) * Ncol + c) = h1;
            } else {
                float2 v0 = { p0, p1 }, v1 = { p2, p3 };
                *(float2*)((float*)C + (size_t)r * Ncol + c)       = v0;
                *(float2*)((float*)C + (size_t)(r + 8) * Ncol + c) = v1;
            }
        }
    }
}

// ---------------------------------------------------------------------------
// f32 -> f16 convert (for x)
// ---------------------------------------------------------------------------
__global__ __launch_bounds__(256)
void convert_h(const float* __restrict__ in, __half* __restrict__ out, int n4)
{
    int i = blockIdx.x * 256 + threadIdx.x;
    if (i < n4) {
        float4 v = ((const float4*)in)[i];
        __half2 h0 = __floats2half2_rn(v.x, v.y);
        __half2 h1 = __floats2half2_rn(v.z, v.w);
        uint2 o = { *(uint32_t*)&h0, *(uint32_t*)&h1 };
        ((uint2*)out)[i] = o;
    }
}

// ---------------------------------------------------------------------------
// Transpose + f16 rounding: out[C][R] = f16(in[R][C])
// ---------------------------------------------------------------------------
__global__ __launch_bounds__(256)
void transpose_k(const float* __restrict__ in, __half* __restrict__ out,
                 int R, int C)
{
    __shared__ float t[32][33];
    const int bx = blockIdx.x * 32, by = blockIdx.y * 32;
    #pragma unroll
    for (int i = 0; i < 4; i++)
        t[threadIdx.y + i * 8][threadIdx.x] =
            in[(size_t)(by + threadIdx.y + i * 8) * C + bx + threadIdx.x];
    __syncthreads();
    #pragma unroll
    for (int i = 0; i < 4; i++)
        out[(size_t)(bx + threadIdx.y + i * 8) * R + by + threadIdx.x] =
            __float2half_rn(t[threadIdx.x][threadIdx.y + i * 8]);
}

// ---------------------------------------------------------------------------
// Middle op (math proven since R3; P fp16 since R14):
//   p = softmax_16(P0 row); Q[b,n,d*64+s] = sum_a p[a]*P1[b,n+a+1,d-1-a,s]
// ---------------------------------------------------------------------------
__global__ __launch_bounds__(256)
void middle_kernel(const __half* __restrict__ P, __half* __restrict__ Q)
{
    const int s   = threadIdx.x & 63;
    const int sub = threadIdx.x >> 6;
    const int bn  = blockIdx.x * 4 + sub;
    const int n   = bn & (NN - 1);
    const int t   = n & 15;
    const int g   = n >> 4;
    const bool last = (g == (NN / 16) - 1);

    const __half* base = P + (size_t)bn * (2 * ALLC) + s;

    float v[16];
    float m = -1e30f;
    #pragma unroll
    for (int k = 0; k < 16; k++) { v[k] = __half2float(base[k * 64]); m = fmaxf(m, v[k]); }
    float sum = 0.f;
    #pragma unroll
    for (int k = 0; k < 16; k++) { v[k] = __expf(v[k] - m); sum += v[k]; }
    const float inv = 1.0f / sum;

    float out[16];
    #pragma unroll
    for (int d = 0; d < 16; d++) out[d] = 0.f;

    const __half* r0 = base + ALLC + 2 * ALLC;

    if (!last) {
        #pragma unroll
        for (int a = 0; a < 15; a++) {
            const float pa = v[a] * inv;
            const __half* ra = r0 + (size_t)a * (2 * ALLC);
            #pragma unroll
            for (int c = 0; c < 15 - a; c++)
                out[a + 1 + c] += pa * __half2float(ra[c * 64]);
        }
    } else {
        const int dmax = 15 - t;
        #pragma unroll
        for (int a = 0; a < 15; a++) {
            const float pa = v[a] * inv;
            const __half* ra = r0 + (size_t)a * (2 * ALLC);
            #pragma unroll
            for (int c = 0; c < 15 - a; c++)
                if (a + 1 + c <= dmax)
                    out[a + 1 + c] += pa * __half2float(ra[c * 64]);
        }
    }

    __half* q = Q + (size_t)bn * ALLC + s;
    #pragma unroll
    for (int d = 0; d < 16; d++) q[d * 64] = __float2half_rn(out[d]);
}

// ---------------------------------------------------------------------------
extern "C" void kernel_launch(void* const* d_in, const int* in_sizes, int n_in,
                              void* d_out, int out_size)
{
    const float* x   = (const float*)d_in[0];
    const float* W_r = (const float*)d_in[1];
    const float* b_r = (const float*)d_in[2];
    const float* W_w = (const float*)d_in[3];
    const float* b_w = (const float*)d_in[4];
    float* out = (float*)d_out;

    __half *P, *Q, *xh, *Wrt, *Wwt;
    cudaGetSymbolAddress((void**)&P,   g_P);
    cudaGetSymbolAddress((void**)&Q,   g_Q);
    cudaGetSymbolAddress((void**)&xh,  g_xh);
    cudaGetSymbolAddress((void**)&Wrt, g_Wrt);
    cudaGetSymbolAddress((void**)&Wwt, g_Wwt);

    cudaFuncSetAttribute(gemm_f16<__half>,
                         cudaFuncAttributeMaxDynamicSharedMemorySize, GEMM_SMEM);
    cudaFuncSetAttribute(gemm_f16<float>,
                         cudaFuncAttributeMaxDynamicSharedMemorySize, GEMM_SMEM);

    // x -> fp16; weight transposes (+ fp16 rounding)
    const int n4 = MROWS * PD / 4;
    convert_h<<<(n4 + 255) / 256, 256>>>(x, xh, n4);
    transpose_k<<<dim3(2 * ALLC / 32, PD / 32), dim3(32, 8)>>>(W_r, Wrt, PD, 2 * ALLC);
    transpose_k<<<dim3(PD / 32, ALLC / 32),     dim3(32, 8)>>>(W_w, Wwt, ALLC, PD);

    // GEMM1: P(fp16) = x @ W_r + b_r   (16384 x 2048 x 1024)
    gemm_f16<__half><<<dim3(2 * ALLC / 128, MROWS / 128), 128, GEMM_SMEM>>>(
        xh, Wrt, b_r, P, 2 * ALLC, PD);

    // Middle: softmax + stencil -> Q (fp16)
    middle_kernel<<<MROWS / 4, 256>>>(P, Q);

    // GEMM2: out(f32) = Q @ W_w + b_w  (16384 x 1024 x 1024)
    gemm_f16<float><<<dim3(PD / 128, MROWS / 128), 128, GEMM_SMEM>>>(
        Q, Wwt, b_w, out, PD, ALLC);
}